// round 1
// baseline (speedup 1.0000x reference)
#include <cuda_runtime.h>
#include <math.h>

// Problem constants (verified against reference: N=1,500,000, E=12,000,000)
#define NN 1500000
#define EE 12000000
#define STRIDE 12   // 9 features padded to 12 floats (48B) for float4 alignment

// Scratch (device globals -- no allocation allowed)
__device__ float g_hx[(size_t)NN * STRIDE];   // node features after lin_x (padded)
__device__ float g_agg[(size_t)NN * STRIDE];  // scatter-add accumulator (padded)

// ---------------------------------------------------------------------------
// K0: hx = Wx1 * x + bx1 (conv1 input transform; x is 1-dim), zero agg
// ---------------------------------------------------------------------------
__global__ void k_init(const float* __restrict__ x,
                       const float* __restrict__ Wx1,
                       const float* __restrict__ bx1, int n) {
    int i = blockIdx.x * blockDim.x + threadIdx.x;
    if (i >= n) return;
    float xv = x[i];
    float h[12];
#pragma unroll
    for (int j = 0; j < 9; j++) h[j] = fmaf(Wx1[j], xv, bx1[j]);
    h[9] = h[10] = h[11] = 0.f;
    float4* hp = (float4*)(g_hx + (size_t)i * STRIDE);
    hp[0] = make_float4(h[0], h[1], h[2], h[3]);
    hp[1] = make_float4(h[4], h[5], h[6], h[7]);
    hp[2] = make_float4(h[8], h[9], h[10], h[11]);
    float4 z = make_float4(0.f, 0.f, 0.f, 0.f);
    float4* ap = (float4*)(g_agg + (size_t)i * STRIDE);
    ap[0] = z; ap[1] = z; ap[2] = z;
}

// ---------------------------------------------------------------------------
// Edge kernel: msg = hx[src] * (We*attr + be); agg[dst] += msg (vector red)
// 4 edges per thread, vectorized loads.
// ---------------------------------------------------------------------------
__device__ __forceinline__ void red_v4(float* p, float a, float b, float c, float d) {
    asm volatile("red.global.add.v4.f32 [%0], {%1,%2,%3,%4};"
                 :: "l"(p), "f"(a), "f"(b), "f"(c), "f"(d) : "memory");
}

__global__ void k_edge(const int* __restrict__ ei,
                       const float* __restrict__ attr,
                       const float* __restrict__ We,
                       const float* __restrict__ be, int E) {
    __shared__ float sWe[18];
    __shared__ float sbe[9];
    if (threadIdx.x < 18) sWe[threadIdx.x] = We[threadIdx.x];
    if (threadIdx.x < 9)  sbe[threadIdx.x] = be[threadIdx.x];
    __syncthreads();

    int t  = blockIdx.x * blockDim.x + threadIdx.x;
    int e0 = t * 4;
    if (e0 >= E) return;

    int4 s4 = *(const int4*)(ei + e0);
    int4 d4 = *(const int4*)(ei + E + e0);
    float4 a0 = *(const float4*)(attr + (size_t)e0 * 2);
    float4 a1 = *(const float4*)(attr + (size_t)e0 * 2 + 4);

    int   src[4] = {s4.x, s4.y, s4.z, s4.w};
    int   dst[4] = {d4.x, d4.y, d4.z, d4.w};
    float ax[4]  = {a0.x, a0.z, a1.x, a1.z};
    float ay[4]  = {a0.y, a0.w, a1.y, a1.w};

    // batch the random gathers first so their latency overlaps
    float4 H0[4], H1[4], H2[4];
#pragma unroll
    for (int k = 0; k < 4; k++) {
        const float4* hp = (const float4*)(g_hx + (size_t)src[k] * STRIDE);
        H0[k] = __ldg(hp);
        H1[k] = __ldg(hp + 1);
        H2[k] = __ldg(hp + 2);
    }

#pragma unroll
    for (int k = 0; k < 4; k++) {
        float ew[9];
#pragma unroll
        for (int j = 0; j < 9; j++)
            ew[j] = fmaf(sWe[2 * j], ax[k], fmaf(sWe[2 * j + 1], ay[k], sbe[j]));
        float m0 = H0[k].x * ew[0], m1 = H0[k].y * ew[1];
        float m2 = H0[k].z * ew[2], m3 = H0[k].w * ew[3];
        float m4 = H1[k].x * ew[4], m5 = H1[k].y * ew[5];
        float m6 = H1[k].z * ew[6], m7 = H1[k].w * ew[7];
        float m8 = H2[k].x * ew[8];
        float* ag = g_agg + (size_t)dst[k] * STRIDE;
        red_v4(ag,     m0, m1, m2, m3);
        red_v4(ag + 4, m4, m5, m6, m7);
        atomicAdd(ag + 8, m8);
    }
}

// ---------------------------------------------------------------------------
// Fused node kernel: r = relu(Wo*agg + bo); hx_next = Wxn*r + bxn; agg = 0
// ---------------------------------------------------------------------------
__global__ void k_node(const float* __restrict__ Wo, const float* __restrict__ bo,
                       const float* __restrict__ Wxn, const float* __restrict__ bxn,
                       int n) {
    __shared__ float sWo[81], sbo[9], sWx[81], sbx[9];
    {
        int tx = threadIdx.x;
        if (tx < 81)                sWo[tx]        = Wo[tx];
        else if (tx < 90)           sbo[tx - 81]   = bo[tx - 81];
        else if (tx < 171)          sWx[tx - 90]   = Wxn[tx - 90];
        else if (tx < 180)          sbx[tx - 171]  = bxn[tx - 171];
    }
    __syncthreads();

    int i = blockIdx.x * blockDim.x + threadIdx.x;
    if (i >= n) return;

    float4* ap = (float4*)(g_agg + (size_t)i * STRIDE);
    float4 A0 = ap[0], A1 = ap[1], A2 = ap[2];
    float acc[9] = {A0.x, A0.y, A0.z, A0.w, A1.x, A1.y, A1.z, A1.w, A2.x};

    float r[9];
#pragma unroll
    for (int o = 0; o < 9; o++) {
        float s = sbo[o];
#pragma unroll
        for (int j = 0; j < 9; j++) s = fmaf(sWo[o * 9 + j], acc[j], s);
        r[o] = fmaxf(s, 0.f);
    }

    float h[12];
#pragma unroll
    for (int o = 0; o < 9; o++) {
        float s = sbx[o];
#pragma unroll
        for (int j = 0; j < 9; j++) s = fmaf(sWx[o * 9 + j], r[j], s);
        h[o] = s;
    }
    h[9] = h[10] = h[11] = 0.f;

    float4* hp = (float4*)(g_hx + (size_t)i * STRIDE);
    hp[0] = make_float4(h[0], h[1], h[2], h[3]);
    hp[1] = make_float4(h[4], h[5], h[6], h[7]);
    hp[2] = make_float4(h[8], h[9], h[10], h[11]);

    float4 z = make_float4(0.f, 0.f, 0.f, 0.f);
    ap[0] = z; ap[1] = z; ap[2] = z;
}

// ---------------------------------------------------------------------------
// Head kernel: per tracklet (6 nodes): o = relu(Wo3*agg+bo3) [4 each] ->
// v[24] -> relu(W1*v+b1)[8] -> W2*y+b2[4] -> log_softmax -> out
// ---------------------------------------------------------------------------
__global__ void k_head(const float* __restrict__ Wo3, const float* __restrict__ bo3,
                       const float* __restrict__ W1,  const float* __restrict__ b1,
                       const float* __restrict__ W2,  const float* __restrict__ b2,
                       float* __restrict__ out, int T) {
    __shared__ float sWo3[36], sbo3[4], sW1[192], sb1[8], sW2[32], sb2[4];
    for (int j = threadIdx.x; j < 36;  j += blockDim.x) sWo3[j] = Wo3[j];
    for (int j = threadIdx.x; j < 4;   j += blockDim.x) sbo3[j] = bo3[j];
    for (int j = threadIdx.x; j < 192; j += blockDim.x) sW1[j]  = W1[j];
    for (int j = threadIdx.x; j < 8;   j += blockDim.x) sb1[j]  = b1[j];
    for (int j = threadIdx.x; j < 32;  j += blockDim.x) sW2[j]  = W2[j];
    for (int j = threadIdx.x; j < 4;   j += blockDim.x) sb2[j]  = b2[j];
    __syncthreads();

    int t = blockIdx.x * blockDim.x + threadIdx.x;
    if (t >= T) return;

    float v[24];
#pragma unroll
    for (int k = 0; k < 6; k++) {
        const float4* ap = (const float4*)(g_agg + (size_t)(t * 6 + k) * STRIDE);
        float4 A0 = __ldg(ap), A1 = __ldg(ap + 1), A2 = __ldg(ap + 2);
        float acc[9] = {A0.x, A0.y, A0.z, A0.w, A1.x, A1.y, A1.z, A1.w, A2.x};
#pragma unroll
        for (int o = 0; o < 4; o++) {
            float s = sbo3[o];
#pragma unroll
            for (int j = 0; j < 9; j++) s = fmaf(sWo3[o * 9 + j], acc[j], s);
            v[k * 4 + o] = fmaxf(s, 0.f);
        }
    }

    float y1[8];
#pragma unroll
    for (int o = 0; o < 8; o++) {
        float s = sb1[o];
#pragma unroll
        for (int j = 0; j < 24; j++) s = fmaf(sW1[o * 24 + j], v[j], s);
        y1[o] = fmaxf(s, 0.f);
    }

    float y2[4];
#pragma unroll
    for (int o = 0; o < 4; o++) {
        float s = sb2[o];
#pragma unroll
        for (int j = 0; j < 8; j++) s = fmaf(sW2[o * 8 + j], y1[j], s);
        y2[o] = s;
    }

    float mx = fmaxf(fmaxf(y2[0], y2[1]), fmaxf(y2[2], y2[3]));
    float se = expf(y2[0] - mx) + expf(y2[1] - mx) + expf(y2[2] - mx) + expf(y2[3] - mx);
    float lse = mx + logf(se);

    float4 o4 = make_float4(y2[0] - lse, y2[1] - lse, y2[2] - lse, y2[3] - lse);
    *(float4*)(out + (size_t)t * 4) = o4;
}

// ---------------------------------------------------------------------------
extern "C" void kernel_launch(void* const* d_in, const int* in_sizes, int n_in,
                              void* d_out, int out_size) {
    const float* x    = (const float*)d_in[0];
    const int*   ei   = (const int*)  d_in[1];
    const float* attr = (const float*)d_in[2];
    const float* Wx1  = (const float*)d_in[3];
    const float* bx1  = (const float*)d_in[4];
    const float* We1  = (const float*)d_in[5];
    const float* be1  = (const float*)d_in[6];
    const float* Wo1  = (const float*)d_in[7];
    const float* bo1  = (const float*)d_in[8];
    const float* Wx2  = (const float*)d_in[9];
    const float* bx2  = (const float*)d_in[10];
    const float* We2  = (const float*)d_in[11];
    const float* be2  = (const float*)d_in[12];
    const float* Wo2  = (const float*)d_in[13];
    const float* bo2  = (const float*)d_in[14];
    const float* Wx3  = (const float*)d_in[15];
    const float* bx3  = (const float*)d_in[16];
    const float* We3  = (const float*)d_in[17];
    const float* be3  = (const float*)d_in[18];
    const float* Wo3  = (const float*)d_in[19];
    const float* bo3  = (const float*)d_in[20];
    const float* W1   = (const float*)d_in[21];
    const float* b1   = (const float*)d_in[22];
    const float* W2   = (const float*)d_in[23];
    const float* b2   = (const float*)d_in[24];

    const int N = in_sizes[0];          // 1,500,000
    const int E = in_sizes[2] / 2;      // 12,000,000
    const int T = N / 6;                // 250,000 tracklets

    const int TB = 256;
    int nodeBlocks = (N + TB - 1) / TB;
    int edgeBlocks = (E / 4 + TB - 1) / TB;

    // conv1
    k_init<<<nodeBlocks, TB>>>(x, Wx1, bx1, N);
    k_edge<<<edgeBlocks, TB>>>(ei, attr, We1, be1, E);
    k_node<<<nodeBlocks, TB>>>(Wo1, bo1, Wx2, bx2, N);
    // conv2
    k_edge<<<edgeBlocks, TB>>>(ei, attr, We2, be2, E);
    k_node<<<nodeBlocks, TB>>>(Wo2, bo2, Wx3, bx3, N);
    // conv3 + head
    k_edge<<<edgeBlocks, TB>>>(ei, attr, We3, be3, E);
    k_head<<<(T + TB - 1) / TB, TB>>>(Wo3, bo3, W1, b1, W2, b2, (float*)d_out, T);
}

// round 3
// speedup vs baseline: 1.0706x; 1.0706x over previous
#include <cuda_runtime.h>
#include <math.h>

#define NN 1500000
#define EE 12000000
#define STRIDE 12   // hx padded to 12 floats for float4 access

// ---- device scratch (no allocation allowed) ----
__device__ float  g_hxA[(size_t)NN * STRIDE];   // 72 MB
__device__ float  g_hxB[(size_t)NN * STRIDE];   // 72 MB
__device__ float  g_out4[(size_t)NN * 4];       // 24 MB
__device__ int    g_rowptr[NN + 1];
__device__ int    g_cursor[NN];                 // degree counts, then write cursors
__device__ int    g_bsums[1024];
__device__ int    g_psrc[(size_t)EE];           // 48 MB  src sorted by dst
__device__ float2 g_pattr[(size_t)EE];          // 96 MB  (ax,ay) sorted by dst

// ---------------------------------------------------------------------------
// K0: hxA = Wx1*x + bx1 ; cursor = 0
// ---------------------------------------------------------------------------
__global__ void k_init(const float* __restrict__ x,
                       const float* __restrict__ Wx1,
                       const float* __restrict__ bx1, int n) {
    int i = blockIdx.x * blockDim.x + threadIdx.x;
    if (i >= n) return;
    float xv = x[i];
    float h[12];
#pragma unroll
    for (int j = 0; j < 9; j++) h[j] = fmaf(Wx1[j], xv, bx1[j]);
    h[9] = h[10] = h[11] = 0.f;
    float4* hp = (float4*)(g_hxA + (size_t)i * STRIDE);
    hp[0] = make_float4(h[0], h[1], h[2], h[3]);
    hp[1] = make_float4(h[4], h[5], h[6], h[7]);
    hp[2] = make_float4(h[8], h[9], h[10], h[11]);
    g_cursor[i] = 0;
}

// ---------------------------------------------------------------------------
// CSR build: histogram of dst
// ---------------------------------------------------------------------------
__global__ void k_hist(const int* __restrict__ ei, int E) {
    int t = blockIdx.x * blockDim.x + threadIdx.x;
    int e0 = t * 4;
    if (e0 >= E) return;
    int4 d4 = *(const int4*)(ei + E + e0);
    atomicAdd(&g_cursor[d4.x], 1);
    atomicAdd(&g_cursor[d4.y], 1);
    atomicAdd(&g_cursor[d4.z], 1);
    atomicAdd(&g_cursor[d4.w], 1);
}

// ---------------------------------------------------------------------------
// Exclusive scan of degrees -> rowptr (3-phase)
// ---------------------------------------------------------------------------
__global__ void k_scan1(int n) {   // 4096 elems / block (256 thr x 16)
    __shared__ int s[256];
    int tid = threadIdx.x;
    int base = blockIdx.x * 4096 + tid * 16;
    int v[16];
    int sum = 0;
#pragma unroll
    for (int j = 0; j < 16; j++) {
        int idx = base + j;
        v[j] = (idx < n) ? g_cursor[idx] : 0;
        sum += v[j];
    }
    s[tid] = sum;
    __syncthreads();
    for (int off = 1; off < 256; off <<= 1) {
        int t = (tid >= off) ? s[tid - off] : 0;
        __syncthreads();
        s[tid] += t;
        __syncthreads();
    }
    int excl = s[tid] - sum;
    if (tid == 255) g_bsums[blockIdx.x] = s[255];
    int run = excl;
#pragma unroll
    for (int j = 0; j < 16; j++) {
        int idx = base + j;
        if (idx < n) g_rowptr[idx] = run;
        run += v[j];
    }
}

__global__ void k_scan2(int nb) {  // single block of 512, nb <= 512
    __shared__ int s[512];
    int tid = threadIdx.x;
    int val = (tid < nb) ? g_bsums[tid] : 0;
    s[tid] = val;
    __syncthreads();
    for (int off = 1; off < 512; off <<= 1) {
        int t = (tid >= off) ? s[tid - off] : 0;
        __syncthreads();
        s[tid] += t;
        __syncthreads();
    }
    if (tid < nb) g_bsums[tid] = s[tid] - val;  // exclusive block offsets
}

__global__ void k_scan3(int n, int E) {
    int i = blockIdx.x * blockDim.x + threadIdx.x;
    if (i >= n) return;
    int r = g_rowptr[i] + g_bsums[i >> 12];
    g_rowptr[i] = r;
    g_cursor[i] = r;
    if (i == 0) g_rowptr[n] = E;
}

// ---------------------------------------------------------------------------
// Permute edges into dst-sorted order
// ---------------------------------------------------------------------------
__global__ void k_scatter(const int* __restrict__ ei,
                          const float* __restrict__ attr, int E) {
    int t = blockIdx.x * blockDim.x + threadIdx.x;
    int e0 = t * 4;
    if (e0 >= E) return;
    int4 s4 = *(const int4*)(ei + e0);
    int4 d4 = *(const int4*)(ei + E + e0);
    float4 a0 = *(const float4*)(attr + (size_t)e0 * 2);
    float4 a1 = *(const float4*)(attr + (size_t)e0 * 2 + 4);
    int    src[4] = {s4.x, s4.y, s4.z, s4.w};
    int    dst[4] = {d4.x, d4.y, d4.z, d4.w};
    float2 at[4]  = {{a0.x, a0.y}, {a0.z, a0.w}, {a1.x, a1.y}, {a1.z, a1.w}};
#pragma unroll
    for (int k = 0; k < 4; k++) {
        int pos = atomicAdd(&g_cursor[dst[k]], 1);
        g_psrc[pos]  = src[k];
        g_pattr[pos] = at[k];
    }
}

// ---------------------------------------------------------------------------
// Fused conv: per node, aggregate its edge segment (no atomics), then
//   OUT==9: r=relu(Wo*acc+bo); hx_out = Wxn*r + bxn   (feeds next conv)
//   OUT==4: out4 = relu(Wo3*acc+bo3)                  (feeds head)
// ---------------------------------------------------------------------------
template <int OUT>
__global__ void k_conv(const float* __restrict__ We, const float* __restrict__ be,
                       const float* __restrict__ Wo, const float* __restrict__ bo,
                       const float* __restrict__ Wxn, const float* __restrict__ bxn,
                       int srcbuf, int n) {
    __shared__ float sWe[18], sbe[9], sWo[OUT * 9], sbo[OUT], sWx[81], sbx[9];
    for (int j = threadIdx.x; j < 18; j += blockDim.x) sWe[j] = We[j];
    for (int j = threadIdx.x; j < 9;  j += blockDim.x) sbe[j] = be[j];
    for (int j = threadIdx.x; j < OUT * 9; j += blockDim.x) sWo[j] = Wo[j];
    for (int j = threadIdx.x; j < OUT; j += blockDim.x) sbo[j] = bo[j];
    if (OUT == 9) {
        for (int j = threadIdx.x; j < 81; j += blockDim.x) sWx[j] = Wxn[j];
        for (int j = threadIdx.x; j < 9;  j += blockDim.x) sbx[j] = bxn[j];
    }
    __syncthreads();

    int i = blockIdx.x * blockDim.x + threadIdx.x;
    if (i >= n) return;

    const float* __restrict__ hin = srcbuf ? g_hxB : g_hxA;
    int beg = g_rowptr[i];
    int end = g_rowptr[i + 1];

    float acc[9] = {0, 0, 0, 0, 0, 0, 0, 0, 0};

    for (int e = beg; e < end; e += 4) {
        int m = end - e;
        int    sidx[4];
        float2 at[4];
        float4 H0[4], H1[4], H2[4];
#pragma unroll
        for (int k = 0; k < 4; k++) {
            if (k < m) {
                sidx[k] = __ldcs(&g_psrc[e + k]);
                at[k]   = __ldcs(&g_pattr[e + k]);
                const float4* hp = (const float4*)(hin + (size_t)sidx[k] * STRIDE);
                H0[k] = __ldg(hp);
                H1[k] = __ldg(hp + 1);
                H2[k] = __ldg(hp + 2);
            }
        }
#pragma unroll
        for (int k = 0; k < 4; k++) {
            if (k < m) {
                float ax = at[k].x, ay = at[k].y;
                float ew[9];
#pragma unroll
                for (int j = 0; j < 9; j++)
                    ew[j] = fmaf(sWe[2 * j], ax, fmaf(sWe[2 * j + 1], ay, sbe[j]));
                acc[0] = fmaf(H0[k].x, ew[0], acc[0]);
                acc[1] = fmaf(H0[k].y, ew[1], acc[1]);
                acc[2] = fmaf(H0[k].z, ew[2], acc[2]);
                acc[3] = fmaf(H0[k].w, ew[3], acc[3]);
                acc[4] = fmaf(H1[k].x, ew[4], acc[4]);
                acc[5] = fmaf(H1[k].y, ew[5], acc[5]);
                acc[6] = fmaf(H1[k].z, ew[6], acc[6]);
                acc[7] = fmaf(H1[k].w, ew[7], acc[7]);
                acc[8] = fmaf(H2[k].x, ew[8], acc[8]);
            }
        }
    }

    if (OUT == 9) {
        float r[9];
#pragma unroll
        for (int o = 0; o < 9; o++) {
            float s = sbo[o];
#pragma unroll
            for (int j = 0; j < 9; j++) s = fmaf(sWo[o * 9 + j], acc[j], s);
            r[o] = fmaxf(s, 0.f);
        }
        float h[12];
#pragma unroll
        for (int o = 0; o < 9; o++) {
            float s = sbx[o];
#pragma unroll
            for (int j = 0; j < 9; j++) s = fmaf(sWx[o * 9 + j], r[j], s);
            h[o] = s;
        }
        h[9] = h[10] = h[11] = 0.f;
        float* hout = srcbuf ? g_hxA : g_hxB;   // ping-pong
        float4* hp = (float4*)(hout + (size_t)i * STRIDE);
        hp[0] = make_float4(h[0], h[1], h[2], h[3]);
        hp[1] = make_float4(h[4], h[5], h[6], h[7]);
        hp[2] = make_float4(h[8], h[9], h[10], h[11]);
    } else {
        float r[4];
#pragma unroll
        for (int o = 0; o < 4; o++) {
            float s = sbo[o];
#pragma unroll
            for (int j = 0; j < 9; j++) s = fmaf(sWo[o * 9 + j], acc[j], s);
            r[o] = fmaxf(s, 0.f);
        }
        *(float4*)(g_out4 + (size_t)i * 4) = make_float4(r[0], r[1], r[2], r[3]);
    }
}

// ---------------------------------------------------------------------------
// Head: per tracklet: v[24] (already relu'd) -> relu(W1 v+b1) -> W2 y+b2
//       -> log_softmax
// ---------------------------------------------------------------------------
__global__ void k_head(const float* __restrict__ W1, const float* __restrict__ b1,
                       const float* __restrict__ W2, const float* __restrict__ b2,
                       float* __restrict__ out, int T) {
    __shared__ float sW1[192], sb1[8], sW2[32], sb2[4];
    for (int j = threadIdx.x; j < 192; j += blockDim.x) sW1[j] = W1[j];
    for (int j = threadIdx.x; j < 8;   j += blockDim.x) sb1[j] = b1[j];
    for (int j = threadIdx.x; j < 32;  j += blockDim.x) sW2[j] = W2[j];
    for (int j = threadIdx.x; j < 4;   j += blockDim.x) sb2[j] = b2[j];
    __syncthreads();

    int t = blockIdx.x * blockDim.x + threadIdx.x;
    if (t >= T) return;

    float v[24];
    const float4* vp = (const float4*)(g_out4 + (size_t)t * 24);
#pragma unroll
    for (int k = 0; k < 6; k++) {
        float4 q = vp[k];
        v[k * 4 + 0] = q.x; v[k * 4 + 1] = q.y;
        v[k * 4 + 2] = q.z; v[k * 4 + 3] = q.w;
    }

    float y1[8];
#pragma unroll
    for (int o = 0; o < 8; o++) {
        float s = sb1[o];
#pragma unroll
        for (int j = 0; j < 24; j++) s = fmaf(sW1[o * 24 + j], v[j], s);
        y1[o] = fmaxf(s, 0.f);
    }
    float y2[4];
#pragma unroll
    for (int o = 0; o < 4; o++) {
        float s = sb2[o];
#pragma unroll
        for (int j = 0; j < 8; j++) s = fmaf(sW2[o * 8 + j], y1[j], s);
        y2[o] = s;
    }
    float mx = fmaxf(fmaxf(y2[0], y2[1]), fmaxf(y2[2], y2[3]));
    float se = expf(y2[0] - mx) + expf(y2[1] - mx) + expf(y2[2] - mx) + expf(y2[3] - mx);
    float lse = mx + logf(se);
    *(float4*)(out + (size_t)t * 4) =
        make_float4(y2[0] - lse, y2[1] - lse, y2[2] - lse, y2[3] - lse);
}

// ---------------------------------------------------------------------------
extern "C" void kernel_launch(void* const* d_in, const int* in_sizes, int n_in,
                              void* d_out, int out_size) {
    const float* x    = (const float*)d_in[0];
    const int*   ei   = (const int*)  d_in[1];
    const float* attr = (const float*)d_in[2];
    const float* Wx1  = (const float*)d_in[3];
    const float* bx1  = (const float*)d_in[4];
    const float* We1  = (const float*)d_in[5];
    const float* be1  = (const float*)d_in[6];
    const float* Wo1  = (const float*)d_in[7];
    const float* bo1  = (const float*)d_in[8];
    const float* Wx2  = (const float*)d_in[9];
    const float* bx2  = (const float*)d_in[10];
    const float* We2  = (const float*)d_in[11];
    const float* be2  = (const float*)d_in[12];
    const float* Wo2  = (const float*)d_in[13];
    const float* bo2  = (const float*)d_in[14];
    const float* Wx3  = (const float*)d_in[15];
    const float* bx3  = (const float*)d_in[16];
    const float* We3  = (const float*)d_in[17];
    const float* be3  = (const float*)d_in[18];
    const float* Wo3  = (const float*)d_in[19];
    const float* bo3  = (const float*)d_in[20];
    const float* W1   = (const float*)d_in[21];
    const float* b1   = (const float*)d_in[22];
    const float* W2   = (const float*)d_in[23];
    const float* b2   = (const float*)d_in[24];

    const int N = in_sizes[0];       // 1,500,000
    const int E = in_sizes[2] / 2;   // 12,000,000
    const int T = N / 6;

    const int TB = 256;
    int nodeBlocks = (N + TB - 1) / TB;
    int edgeBlocks = (E / 4 + TB - 1) / TB;
    int scanBlocks = (N + 4095) / 4096;

    // init + CSR build (reused by all 3 convs)
    k_init<<<nodeBlocks, TB>>>(x, Wx1, bx1, N);
    k_hist<<<edgeBlocks, TB>>>(ei, E);
    k_scan1<<<scanBlocks, TB>>>(N);
    k_scan2<<<1, 512>>>(scanBlocks);
    k_scan3<<<nodeBlocks, TB>>>(N, E);
    k_scatter<<<edgeBlocks, TB>>>(ei, attr, E);

    // conv1: hxA -> hxB ; conv2: hxB -> hxA ; conv3: hxA -> out4
    k_conv<9><<<nodeBlocks, TB>>>(We1, be1, Wo1, bo1, Wx2, bx2, 0, N);
    k_conv<9><<<nodeBlocks, TB>>>(We2, be2, Wo2, bo2, Wx3, bx3, 1, N);
    k_conv<4><<<nodeBlocks, TB>>>(We3, be3, Wo3, bo3, nullptr, nullptr, 0, N);

    k_head<<<(T + TB - 1) / TB, TB>>>(W1, b1, W2, b2, (float*)d_out, T);
}

// round 4
// speedup vs baseline: 1.2100x; 1.1303x over previous
#include <cuda_runtime.h>
#include <math.h>

#define NN 1500000
#define EE 12000000
#define STRIDE 12   // hx padded to 12 floats for float4 access
#define CH 2048     // staged edge records per chunk (32KB smem)

// ---- device scratch (no allocation allowed) ----
__device__ float  g_hxA[(size_t)NN * STRIDE];   // 72 MB
__device__ float  g_hxB[(size_t)NN * STRIDE];   // 72 MB
__device__ float  g_out4[(size_t)NN * 4];       // 24 MB
__device__ int    g_rowptr[NN + 1];
__device__ int    g_cursor[NN];
__device__ int    g_bsums[1024];
__device__ float4 g_perm[(size_t)EE];           // 192 MB (src,ax,ay,0) sorted by dst

// ---------------------------------------------------------------------------
__global__ void k_init(const float* __restrict__ x,
                       const float* __restrict__ Wx1,
                       const float* __restrict__ bx1, int n) {
    int i = blockIdx.x * blockDim.x + threadIdx.x;
    if (i >= n) return;
    float xv = x[i];
    float h[12];
#pragma unroll
    for (int j = 0; j < 9; j++) h[j] = fmaf(Wx1[j], xv, bx1[j]);
    h[9] = h[10] = h[11] = 0.f;
    float4* hp = (float4*)(g_hxA + (size_t)i * STRIDE);
    hp[0] = make_float4(h[0], h[1], h[2], h[3]);
    hp[1] = make_float4(h[4], h[5], h[6], h[7]);
    hp[2] = make_float4(h[8], h[9], h[10], h[11]);
    g_cursor[i] = 0;
}

// ---------------------------------------------------------------------------
__global__ void k_hist(const int* __restrict__ ei, int E) {
    int t = blockIdx.x * blockDim.x + threadIdx.x;
    int e0 = t * 4;
    if (e0 >= E) return;
    int4 d4 = *(const int4*)(ei + E + e0);
    atomicAdd(&g_cursor[d4.x], 1);
    atomicAdd(&g_cursor[d4.y], 1);
    atomicAdd(&g_cursor[d4.z], 1);
    atomicAdd(&g_cursor[d4.w], 1);
}

// ---------------------------------------------------------------------------
__global__ void k_scan1(int n) {   // 4096 elems / block
    __shared__ int s[256];
    int tid = threadIdx.x;
    int base = blockIdx.x * 4096 + tid * 16;
    int v[16];
    int sum = 0;
#pragma unroll
    for (int j = 0; j < 16; j++) {
        int idx = base + j;
        v[j] = (idx < n) ? g_cursor[idx] : 0;
        sum += v[j];
    }
    s[tid] = sum;
    __syncthreads();
    for (int off = 1; off < 256; off <<= 1) {
        int t = (tid >= off) ? s[tid - off] : 0;
        __syncthreads();
        s[tid] += t;
        __syncthreads();
    }
    int excl = s[tid] - sum;
    if (tid == 255) g_bsums[blockIdx.x] = s[255];
    int run = excl;
#pragma unroll
    for (int j = 0; j < 16; j++) {
        int idx = base + j;
        if (idx < n) g_rowptr[idx] = run;
        run += v[j];
    }
}

__global__ void k_scan2(int nb) {
    __shared__ int s[512];
    int tid = threadIdx.x;
    int val = (tid < nb) ? g_bsums[tid] : 0;
    s[tid] = val;
    __syncthreads();
    for (int off = 1; off < 512; off <<= 1) {
        int t = (tid >= off) ? s[tid - off] : 0;
        __syncthreads();
        s[tid] += t;
        __syncthreads();
    }
    if (tid < nb) g_bsums[tid] = s[tid] - val;
}

__global__ void k_scan3(int n, int E) {
    int i = blockIdx.x * blockDim.x + threadIdx.x;
    if (i >= n) return;
    int r = g_rowptr[i] + g_bsums[i >> 12];
    g_rowptr[i] = r;
    g_cursor[i] = r;
    if (i == 0) g_rowptr[n] = E;
}

// ---------------------------------------------------------------------------
// Permute edges into dst-sorted order; ONE 16B store per edge.
// ---------------------------------------------------------------------------
__global__ void k_scatter(const int* __restrict__ ei,
                          const float* __restrict__ attr, int E) {
    int t = blockIdx.x * blockDim.x + threadIdx.x;
    int e0 = t * 4;
    if (e0 >= E) return;
    int4 s4 = *(const int4*)(ei + e0);
    int4 d4 = *(const int4*)(ei + E + e0);
    float4 a0 = *(const float4*)(attr + (size_t)e0 * 2);
    float4 a1 = *(const float4*)(attr + (size_t)e0 * 2 + 4);
    int   src[4] = {s4.x, s4.y, s4.z, s4.w};
    int   dst[4] = {d4.x, d4.y, d4.z, d4.w};
    float ax[4]  = {a0.x, a0.z, a1.x, a1.z};
    float ay[4]  = {a0.y, a0.w, a1.y, a1.w};
#pragma unroll
    for (int k = 0; k < 4; k++) {
        int pos = atomicAdd(&g_cursor[dst[k]], 1);
        g_perm[pos] = make_float4(__int_as_float(src[k]), ax[k], ay[k], 0.f);
    }
}

// ---------------------------------------------------------------------------
// Fused conv with SMEM-staged edge records (coalesced perm reads).
// Block covers 256 consecutive nodes; its CSR window is staged chunk-wise.
// ---------------------------------------------------------------------------
template <int OUT>
__global__ void k_conv(const float* __restrict__ We, const float* __restrict__ be,
                       const float* __restrict__ Wo, const float* __restrict__ bo,
                       const float* __restrict__ Wxn, const float* __restrict__ bxn,
                       int srcbuf, int n) {
    __shared__ float4 sbuf[CH];
    __shared__ float sWe[18], sbe[9], sWo[OUT * 9], sbo[OUT], sWx[81], sbx[9];
    for (int j = threadIdx.x; j < 18; j += blockDim.x) sWe[j] = We[j];
    for (int j = threadIdx.x; j < 9;  j += blockDim.x) sbe[j] = be[j];
    for (int j = threadIdx.x; j < OUT * 9; j += blockDim.x) sWo[j] = Wo[j];
    for (int j = threadIdx.x; j < OUT; j += blockDim.x) sbo[j] = bo[j];
    if (OUT == 9) {
        for (int j = threadIdx.x; j < 81; j += blockDim.x) sWx[j] = Wxn[j];
        for (int j = threadIdx.x; j < 9;  j += blockDim.x) sbx[j] = bxn[j];
    }

    int b0 = blockIdx.x * blockDim.x;
    int i  = b0 + threadIdx.x;
    int beg = 0, end = 0;
    if (i < n) { beg = __ldg(&g_rowptr[i]); end = __ldg(&g_rowptr[i + 1]); }
    int lastNode = min(b0 + (int)blockDim.x, n);
    int beg_blk = __ldg(&g_rowptr[b0]);
    int end_blk = __ldg(&g_rowptr[lastNode]);

    const float* __restrict__ hin = srcbuf ? g_hxB : g_hxA;
    float acc[9] = {0, 0, 0, 0, 0, 0, 0, 0, 0};

    for (int c0 = beg_blk; c0 < end_blk; c0 += CH) {
        int cnt = min(CH, end_blk - c0);
        __syncthreads();
        for (int j = threadIdx.x; j < cnt; j += blockDim.x)
            sbuf[j] = __ldcs(&g_perm[c0 + j]);
        __syncthreads();

        int lo = max(beg, c0) - c0;
        int hi = min(end, c0 + cnt) - c0;
        int e = lo;
        for (; e + 2 <= hi; e += 2) {
            float4 r0 = sbuf[e], r1 = sbuf[e + 1];
            const float4* h0 =
                (const float4*)(hin + (size_t)__float_as_int(r0.x) * STRIDE);
            const float4* h1 =
                (const float4*)(hin + (size_t)__float_as_int(r1.x) * STRIDE);
            float4 A0 = __ldg(h0), A1 = __ldg(h0 + 1), A2 = __ldg(h0 + 2);
            float4 B0 = __ldg(h1), B1 = __ldg(h1 + 1), B2 = __ldg(h1 + 2);
            float ew[9];
#pragma unroll
            for (int j = 0; j < 9; j++)
                ew[j] = fmaf(sWe[2 * j], r0.y, fmaf(sWe[2 * j + 1], r0.z, sbe[j]));
            acc[0] = fmaf(A0.x, ew[0], acc[0]);
            acc[1] = fmaf(A0.y, ew[1], acc[1]);
            acc[2] = fmaf(A0.z, ew[2], acc[2]);
            acc[3] = fmaf(A0.w, ew[3], acc[3]);
            acc[4] = fmaf(A1.x, ew[4], acc[4]);
            acc[5] = fmaf(A1.y, ew[5], acc[5]);
            acc[6] = fmaf(A1.z, ew[6], acc[6]);
            acc[7] = fmaf(A1.w, ew[7], acc[7]);
            acc[8] = fmaf(A2.x, ew[8], acc[8]);
#pragma unroll
            for (int j = 0; j < 9; j++)
                ew[j] = fmaf(sWe[2 * j], r1.y, fmaf(sWe[2 * j + 1], r1.z, sbe[j]));
            acc[0] = fmaf(B0.x, ew[0], acc[0]);
            acc[1] = fmaf(B0.y, ew[1], acc[1]);
            acc[2] = fmaf(B0.z, ew[2], acc[2]);
            acc[3] = fmaf(B0.w, ew[3], acc[3]);
            acc[4] = fmaf(B1.x, ew[4], acc[4]);
            acc[5] = fmaf(B1.y, ew[5], acc[5]);
            acc[6] = fmaf(B1.z, ew[6], acc[6]);
            acc[7] = fmaf(B1.w, ew[7], acc[7]);
            acc[8] = fmaf(B2.x, ew[8], acc[8]);
        }
        if (e < hi) {
            float4 r0 = sbuf[e];
            const float4* h0 =
                (const float4*)(hin + (size_t)__float_as_int(r0.x) * STRIDE);
            float4 A0 = __ldg(h0), A1 = __ldg(h0 + 1), A2 = __ldg(h0 + 2);
            float ew[9];
#pragma unroll
            for (int j = 0; j < 9; j++)
                ew[j] = fmaf(sWe[2 * j], r0.y, fmaf(sWe[2 * j + 1], r0.z, sbe[j]));
            acc[0] = fmaf(A0.x, ew[0], acc[0]);
            acc[1] = fmaf(A0.y, ew[1], acc[1]);
            acc[2] = fmaf(A0.z, ew[2], acc[2]);
            acc[3] = fmaf(A0.w, ew[3], acc[3]);
            acc[4] = fmaf(A1.x, ew[4], acc[4]);
            acc[5] = fmaf(A1.y, ew[5], acc[5]);
            acc[6] = fmaf(A1.z, ew[6], acc[6]);
            acc[7] = fmaf(A1.w, ew[7], acc[7]);
            acc[8] = fmaf(A2.x, ew[8], acc[8]);
        }
    }

    if (i >= n) return;

    if (OUT == 9) {
        float r[9];
#pragma unroll
        for (int o = 0; o < 9; o++) {
            float s = sbo[o];
#pragma unroll
            for (int j = 0; j < 9; j++) s = fmaf(sWo[o * 9 + j], acc[j], s);
            r[o] = fmaxf(s, 0.f);
        }
        float h[12];
#pragma unroll
        for (int o = 0; o < 9; o++) {
            float s = sbx[o];
#pragma unroll
            for (int j = 0; j < 9; j++) s = fmaf(sWx[o * 9 + j], r[j], s);
            h[o] = s;
        }
        h[9] = h[10] = h[11] = 0.f;
        float* hout = srcbuf ? g_hxA : g_hxB;
        float4* hp = (float4*)(hout + (size_t)i * STRIDE);
        hp[0] = make_float4(h[0], h[1], h[2], h[3]);
        hp[1] = make_float4(h[4], h[5], h[6], h[7]);
        hp[2] = make_float4(h[8], h[9], h[10], h[11]);
    } else {
        float r[4];
#pragma unroll
        for (int o = 0; o < 4; o++) {
            float s = sbo[o];
#pragma unroll
            for (int j = 0; j < 9; j++) s = fmaf(sWo[o * 9 + j], acc[j], s);
            r[o] = fmaxf(s, 0.f);
        }
        *(float4*)(g_out4 + (size_t)i * 4) = make_float4(r[0], r[1], r[2], r[3]);
    }
}

// ---------------------------------------------------------------------------
__global__ void k_head(const float* __restrict__ W1, const float* __restrict__ b1,
                       const float* __restrict__ W2, const float* __restrict__ b2,
                       float* __restrict__ out, int T) {
    __shared__ float sW1[192], sb1[8], sW2[32], sb2[4];
    for (int j = threadIdx.x; j < 192; j += blockDim.x) sW1[j] = W1[j];
    for (int j = threadIdx.x; j < 8;   j += blockDim.x) sb1[j] = b1[j];
    for (int j = threadIdx.x; j < 32;  j += blockDim.x) sW2[j] = W2[j];
    for (int j = threadIdx.x; j < 4;   j += blockDim.x) sb2[j] = b2[j];
    __syncthreads();

    int t = blockIdx.x * blockDim.x + threadIdx.x;
    if (t >= T) return;

    float v[24];
    const float4* vp = (const float4*)(g_out4 + (size_t)t * 24);
#pragma unroll
    for (int k = 0; k < 6; k++) {
        float4 q = vp[k];
        v[k * 4 + 0] = q.x; v[k * 4 + 1] = q.y;
        v[k * 4 + 2] = q.z; v[k * 4 + 3] = q.w;
    }
    float y1[8];
#pragma unroll
    for (int o = 0; o < 8; o++) {
        float s = sb1[o];
#pragma unroll
        for (int j = 0; j < 24; j++) s = fmaf(sW1[o * 24 + j], v[j], s);
        y1[o] = fmaxf(s, 0.f);
    }
    float y2[4];
#pragma unroll
    for (int o = 0; o < 4; o++) {
        float s = sb2[o];
#pragma unroll
        for (int j = 0; j < 8; j++) s = fmaf(sW2[o * 8 + j], y1[j], s);
        y2[o] = s;
    }
    float mx = fmaxf(fmaxf(y2[0], y2[1]), fmaxf(y2[2], y2[3]));
    float se = expf(y2[0] - mx) + expf(y2[1] - mx) + expf(y2[2] - mx) + expf(y2[3] - mx);
    float lse = mx + logf(se);
    *(float4*)(out + (size_t)t * 4) =
        make_float4(y2[0] - lse, y2[1] - lse, y2[2] - lse, y2[3] - lse);
}

// ---------------------------------------------------------------------------
extern "C" void kernel_launch(void* const* d_in, const int* in_sizes, int n_in,
                              void* d_out, int out_size) {
    const float* x    = (const float*)d_in[0];
    const int*   ei   = (const int*)  d_in[1];
    const float* attr = (const float*)d_in[2];
    const float* Wx1  = (const float*)d_in[3];
    const float* bx1  = (const float*)d_in[4];
    const float* We1  = (const float*)d_in[5];
    const float* be1  = (const float*)d_in[6];
    const float* Wo1  = (const float*)d_in[7];
    const float* bo1  = (const float*)d_in[8];
    const float* Wx2  = (const float*)d_in[9];
    const float* bx2  = (const float*)d_in[10];
    const float* We2  = (const float*)d_in[11];
    const float* be2  = (const float*)d_in[12];
    const float* Wo2  = (const float*)d_in[13];
    const float* bo2  = (const float*)d_in[14];
    const float* Wx3  = (const float*)d_in[15];
    const float* bx3  = (const float*)d_in[16];
    const float* We3  = (const float*)d_in[17];
    const float* be3  = (const float*)d_in[18];
    const float* Wo3  = (const float*)d_in[19];
    const float* bo3  = (const float*)d_in[20];
    const float* W1   = (const float*)d_in[21];
    const float* b1   = (const float*)d_in[22];
    const float* W2   = (const float*)d_in[23];
    const float* b2   = (const float*)d_in[24];

    const int N = in_sizes[0];       // 1,500,000
    const int E = in_sizes[2] / 2;   // 12,000,000
    const int T = N / 6;

    const int TB = 256;
    int nodeBlocks = (N + TB - 1) / TB;
    int edgeBlocks = (E / 4 + TB - 1) / TB;
    int scanBlocks = (N + 4095) / 4096;

    k_init<<<nodeBlocks, TB>>>(x, Wx1, bx1, N);
    k_hist<<<edgeBlocks, TB>>>(ei, E);
    k_scan1<<<scanBlocks, TB>>>(N);
    k_scan2<<<1, 512>>>(scanBlocks);
    k_scan3<<<nodeBlocks, TB>>>(N, E);
    k_scatter<<<edgeBlocks, TB>>>(ei, attr, E);

    k_conv<9><<<nodeBlocks, TB>>>(We1, be1, Wo1, bo1, Wx2, bx2, 0, N);
    k_conv<9><<<nodeBlocks, TB>>>(We2, be2, Wo2, bo2, Wx3, bx3, 1, N);
    k_conv<4><<<nodeBlocks, TB>>>(We3, be3, Wo3, bo3, nullptr, nullptr, 0, N);

    k_head<<<(T + TB - 1) / TB, TB>>>(W1, b1, W2, b2, (float*)d_out, T);
}

// round 5
// speedup vs baseline: 1.3715x; 1.1335x over previous
#include <cuda_runtime.h>
#include <cuda_fp16.h>
#include <math.h>

#define NN 1500000
#define EE 12000000
#define HSTRIDE 16  // halves per node record: 9 used + pad -> 32B aligned
#define CH 2048     // staged edge records per chunk (32KB smem)

// ---- device scratch (no allocation allowed) ----
__device__ __half  g_hxA[(size_t)NN * HSTRIDE];  // 48 MB
__device__ __half  g_hxB[(size_t)NN * HSTRIDE];  // 48 MB
__device__ float   g_out4[(size_t)NN * 4];       // 24 MB
__device__ int     g_rowptr[NN + 1];
__device__ int     g_cursor[NN];
__device__ int     g_bsums[1024];
__device__ float4  g_perm[(size_t)EE];           // 192 MB (src,ax,ay,0) by dst

// Pack 9 floats -> fp16 record (uint4 + uint) and store.
__device__ __forceinline__ void store_h9(__half* basePtr, size_t i, const float* h) {
    __half2 p0 = __floats2half2_rn(h[0], h[1]);
    __half2 p1 = __floats2half2_rn(h[2], h[3]);
    __half2 p2 = __floats2half2_rn(h[4], h[5]);
    __half2 p3 = __floats2half2_rn(h[6], h[7]);
    __half2 p4 = __floats2half2_rn(h[8], 0.f);
    uint4 q;
    q.x = *(unsigned int*)&p0;
    q.y = *(unsigned int*)&p1;
    q.z = *(unsigned int*)&p2;
    q.w = *(unsigned int*)&p3;
    unsigned int* rec = (unsigned int*)(basePtr + i * HSTRIDE);
    *(uint4*)rec = q;
    rec[4] = *(unsigned int*)&p4;
}

// Gather 9 fp16 node features -> floats. 2 loads, one 32B sector.
__device__ __forceinline__ void load_h9(const __half* basePtr, size_t i, float* f) {
    const unsigned int* rec = (const unsigned int*)(basePtr + i * HSTRIDE);
    uint4 q = __ldg((const uint4*)rec);
    unsigned int q4 = __ldg(rec + 4);
    float2 a = __half22float2(*(const __half2*)&q.x);
    float2 b = __half22float2(*(const __half2*)&q.y);
    float2 c = __half22float2(*(const __half2*)&q.z);
    float2 d = __half22float2(*(const __half2*)&q.w);
    float2 e = __half22float2(*(const __half2*)&q4);
    f[0] = a.x; f[1] = a.y; f[2] = b.x; f[3] = b.y;
    f[4] = c.x; f[5] = c.y; f[6] = d.x; f[7] = d.y; f[8] = e.x;
}

// ---------------------------------------------------------------------------
__global__ void k_init(const float* __restrict__ x,
                       const float* __restrict__ Wx1,
                       const float* __restrict__ bx1, int n) {
    int i = blockIdx.x * blockDim.x + threadIdx.x;
    if (i >= n) return;
    float xv = x[i];
    float h[9];
#pragma unroll
    for (int j = 0; j < 9; j++) h[j] = fmaf(Wx1[j], xv, bx1[j]);
    store_h9(g_hxA, (size_t)i, h);
    g_cursor[i] = 0;
}

// ---------------------------------------------------------------------------
__global__ void k_hist(const int* __restrict__ ei, int E) {
    int t = blockIdx.x * blockDim.x + threadIdx.x;
    int e0 = t * 4;
    if (e0 >= E) return;
    int4 d4 = *(const int4*)(ei + E + e0);
    atomicAdd(&g_cursor[d4.x], 1);
    atomicAdd(&g_cursor[d4.y], 1);
    atomicAdd(&g_cursor[d4.z], 1);
    atomicAdd(&g_cursor[d4.w], 1);
}

// ---------------------------------------------------------------------------
__global__ void k_scan1(int n) {   // 4096 elems / block
    __shared__ int s[256];
    int tid = threadIdx.x;
    int base = blockIdx.x * 4096 + tid * 16;
    int v[16];
    int sum = 0;
#pragma unroll
    for (int j = 0; j < 16; j++) {
        int idx = base + j;
        v[j] = (idx < n) ? g_cursor[idx] : 0;
        sum += v[j];
    }
    s[tid] = sum;
    __syncthreads();
    for (int off = 1; off < 256; off <<= 1) {
        int t = (tid >= off) ? s[tid - off] : 0;
        __syncthreads();
        s[tid] += t;
        __syncthreads();
    }
    int excl = s[tid] - sum;
    if (tid == 255) g_bsums[blockIdx.x] = s[255];
    int run = excl;
#pragma unroll
    for (int j = 0; j < 16; j++) {
        int idx = base + j;
        if (idx < n) g_rowptr[idx] = run;
        run += v[j];
    }
}

__global__ void k_scan2(int nb) {
    __shared__ int s[512];
    int tid = threadIdx.x;
    int val = (tid < nb) ? g_bsums[tid] : 0;
    s[tid] = val;
    __syncthreads();
    for (int off = 1; off < 512; off <<= 1) {
        int t = (tid >= off) ? s[tid - off] : 0;
        __syncthreads();
        s[tid] += t;
        __syncthreads();
    }
    if (tid < nb) g_bsums[tid] = s[tid] - val;
}

__global__ void k_scan3(int n, int E) {
    int i = blockIdx.x * blockDim.x + threadIdx.x;
    if (i >= n) return;
    int r = g_rowptr[i] + g_bsums[i >> 12];
    g_rowptr[i] = r;
    g_cursor[i] = r;
    if (i == 0) g_rowptr[n] = E;
}

// ---------------------------------------------------------------------------
__global__ void k_scatter(const int* __restrict__ ei,
                          const float* __restrict__ attr, int E) {
    int t = blockIdx.x * blockDim.x + threadIdx.x;
    int e0 = t * 4;
    if (e0 >= E) return;
    int4 s4 = *(const int4*)(ei + e0);
    int4 d4 = *(const int4*)(ei + E + e0);
    float4 a0 = *(const float4*)(attr + (size_t)e0 * 2);
    float4 a1 = *(const float4*)(attr + (size_t)e0 * 2 + 4);
    int   src[4] = {s4.x, s4.y, s4.z, s4.w};
    int   dst[4] = {d4.x, d4.y, d4.z, d4.w};
    float ax[4]  = {a0.x, a0.z, a1.x, a1.z};
    float ay[4]  = {a0.y, a0.w, a1.y, a1.w};
#pragma unroll
    for (int k = 0; k < 4; k++) {
        int pos = atomicAdd(&g_cursor[dst[k]], 1);
        g_perm[pos] = make_float4(__int_as_float(src[k]), ax[k], ay[k], 0.f);
    }
}

// ---------------------------------------------------------------------------
// Fused conv; SMEM-staged edge records + fp16 node gathers (2 wf/edge).
// ---------------------------------------------------------------------------
template <int OUT>
__global__ void k_conv(const float* __restrict__ We, const float* __restrict__ be,
                       const float* __restrict__ Wo, const float* __restrict__ bo,
                       const float* __restrict__ Wxn, const float* __restrict__ bxn,
                       int srcbuf, int n) {
    __shared__ float4 sbuf[CH];
    __shared__ float sWe[18], sbe[9], sWo[OUT * 9], sbo[OUT], sWx[81], sbx[9];
    for (int j = threadIdx.x; j < 18; j += blockDim.x) sWe[j] = We[j];
    for (int j = threadIdx.x; j < 9;  j += blockDim.x) sbe[j] = be[j];
    for (int j = threadIdx.x; j < OUT * 9; j += blockDim.x) sWo[j] = Wo[j];
    for (int j = threadIdx.x; j < OUT; j += blockDim.x) sbo[j] = bo[j];
    if (OUT == 9) {
        for (int j = threadIdx.x; j < 81; j += blockDim.x) sWx[j] = Wxn[j];
        for (int j = threadIdx.x; j < 9;  j += blockDim.x) sbx[j] = bxn[j];
    }

    int b0 = blockIdx.x * blockDim.x;
    int i  = b0 + threadIdx.x;
    int beg = 0, end = 0;
    if (i < n) { beg = __ldg(&g_rowptr[i]); end = __ldg(&g_rowptr[i + 1]); }
    int lastNode = min(b0 + (int)blockDim.x, n);
    int beg_blk = __ldg(&g_rowptr[b0]);
    int end_blk = __ldg(&g_rowptr[lastNode]);

    const __half* __restrict__ hin = srcbuf ? g_hxB : g_hxA;
    float acc[9] = {0, 0, 0, 0, 0, 0, 0, 0, 0};

    for (int c0 = beg_blk; c0 < end_blk; c0 += CH) {
        int cnt = min(CH, end_blk - c0);
        __syncthreads();
        for (int j = threadIdx.x; j < cnt; j += blockDim.x)
            sbuf[j] = __ldcs(&g_perm[c0 + j]);
        __syncthreads();

        int lo = max(beg, c0) - c0;
        int hi = min(end, c0 + cnt) - c0;
        int e = lo;
        for (; e + 2 <= hi; e += 2) {
            float4 r0 = sbuf[e], r1 = sbuf[e + 1];
            float A[9], B[9];
            load_h9(hin, (size_t)__float_as_int(r0.x), A);
            load_h9(hin, (size_t)__float_as_int(r1.x), B);
            float ew[9];
#pragma unroll
            for (int j = 0; j < 9; j++)
                ew[j] = fmaf(sWe[2 * j], r0.y, fmaf(sWe[2 * j + 1], r0.z, sbe[j]));
#pragma unroll
            for (int j = 0; j < 9; j++) acc[j] = fmaf(A[j], ew[j], acc[j]);
#pragma unroll
            for (int j = 0; j < 9; j++)
                ew[j] = fmaf(sWe[2 * j], r1.y, fmaf(sWe[2 * j + 1], r1.z, sbe[j]));
#pragma unroll
            for (int j = 0; j < 9; j++) acc[j] = fmaf(B[j], ew[j], acc[j]);
        }
        if (e < hi) {
            float4 r0 = sbuf[e];
            float A[9];
            load_h9(hin, (size_t)__float_as_int(r0.x), A);
            float ew[9];
#pragma unroll
            for (int j = 0; j < 9; j++)
                ew[j] = fmaf(sWe[2 * j], r0.y, fmaf(sWe[2 * j + 1], r0.z, sbe[j]));
#pragma unroll
            for (int j = 0; j < 9; j++) acc[j] = fmaf(A[j], ew[j], acc[j]);
        }
    }

    if (i >= n) return;

    if (OUT == 9) {
        float r[9];
#pragma unroll
        for (int o = 0; o < 9; o++) {
            float s = sbo[o];
#pragma unroll
            for (int j = 0; j < 9; j++) s = fmaf(sWo[o * 9 + j], acc[j], s);
            r[o] = fmaxf(s, 0.f);
        }
        float h[9];
#pragma unroll
        for (int o = 0; o < 9; o++) {
            float s = sbx[o];
#pragma unroll
            for (int j = 0; j < 9; j++) s = fmaf(sWx[o * 9 + j], r[j], s);
            h[o] = s;
        }
        __half* hout = srcbuf ? g_hxA : g_hxB;   // ping-pong
        store_h9(hout, (size_t)i, h);
    } else {
        float r[4];
#pragma unroll
        for (int o = 0; o < 4; o++) {
            float s = sbo[o];
#pragma unroll
            for (int j = 0; j < 9; j++) s = fmaf(sWo[o * 9 + j], acc[j], s);
            r[o] = fmaxf(s, 0.f);
        }
        *(float4*)(g_out4 + (size_t)i * 4) = make_float4(r[0], r[1], r[2], r[3]);
    }
}

// ---------------------------------------------------------------------------
__global__ void k_head(const float* __restrict__ W1, const float* __restrict__ b1,
                       const float* __restrict__ W2, const float* __restrict__ b2,
                       float* __restrict__ out, int T) {
    __shared__ float sW1[192], sb1[8], sW2[32], sb2[4];
    for (int j = threadIdx.x; j < 192; j += blockDim.x) sW1[j] = W1[j];
    for (int j = threadIdx.x; j < 8;   j += blockDim.x) sb1[j] = b1[j];
    for (int j = threadIdx.x; j < 32;  j += blockDim.x) sW2[j] = W2[j];
    for (int j = threadIdx.x; j < 4;   j += blockDim.x) sb2[j] = b2[j];
    __syncthreads();

    int t = blockIdx.x * blockDim.x + threadIdx.x;
    if (t >= T) return;

    float v[24];
    const float4* vp = (const float4*)(g_out4 + (size_t)t * 24);
#pragma unroll
    for (int k = 0; k < 6; k++) {
        float4 q = vp[k];
        v[k * 4 + 0] = q.x; v[k * 4 + 1] = q.y;
        v[k * 4 + 2] = q.z; v[k * 4 + 3] = q.w;
    }
    float y1[8];
#pragma unroll
    for (int o = 0; o < 8; o++) {
        float s = sb1[o];
#pragma unroll
        for (int j = 0; j < 24; j++) s = fmaf(sW1[o * 24 + j], v[j], s);
        y1[o] = fmaxf(s, 0.f);
    }
    float y2[4];
#pragma unroll
    for (int o = 0; o < 4; o++) {
        float s = sb2[o];
#pragma unroll
        for (int j = 0; j < 8; j++) s = fmaf(sW2[o * 8 + j], y1[j], s);
        y2[o] = s;
    }
    float mx = fmaxf(fmaxf(y2[0], y2[1]), fmaxf(y2[2], y2[3]));
    float se = expf(y2[0] - mx) + expf(y2[1] - mx) + expf(y2[2] - mx) + expf(y2[3] - mx);
    float lse = mx + logf(se);
    *(float4*)(out + (size_t)t * 4) =
        make_float4(y2[0] - lse, y2[1] - lse, y2[2] - lse, y2[3] - lse);
}

// ---------------------------------------------------------------------------
extern "C" void kernel_launch(void* const* d_in, const int* in_sizes, int n_in,
                              void* d_out, int out_size) {
    const float* x    = (const float*)d_in[0];
    const int*   ei   = (const int*)  d_in[1];
    const float* attr = (const float*)d_in[2];
    const float* Wx1  = (const float*)d_in[3];
    const float* bx1  = (const float*)d_in[4];
    const float* We1  = (const float*)d_in[5];
    const float* be1  = (const float*)d_in[6];
    const float* Wo1  = (const float*)d_in[7];
    const float* bo1  = (const float*)d_in[8];
    const float* Wx2  = (const float*)d_in[9];
    const float* bx2  = (const float*)d_in[10];
    const float* We2  = (const float*)d_in[11];
    const float* be2  = (const float*)d_in[12];
    const float* Wo2  = (const float*)d_in[13];
    const float* bo2  = (const float*)d_in[14];
    const float* Wx3  = (const float*)d_in[15];
    const float* bx3  = (const float*)d_in[16];
    const float* We3  = (const float*)d_in[17];
    const float* be3  = (const float*)d_in[18];
    const float* Wo3  = (const float*)d_in[19];
    const float* bo3  = (const float*)d_in[20];
    const float* W1   = (const float*)d_in[21];
    const float* b1   = (const float*)d_in[22];
    const float* W2   = (const float*)d_in[23];
    const float* b2   = (const float*)d_in[24];

    const int N = in_sizes[0];       // 1,500,000
    const int E = in_sizes[2] / 2;   // 12,000,000
    const int T = N / 6;

    const int TB = 256;
    int nodeBlocks = (N + TB - 1) / TB;
    int edgeBlocks = (E / 4 + TB - 1) / TB;
    int scanBlocks = (N + 4095) / 4096;

    k_init<<<nodeBlocks, TB>>>(x, Wx1, bx1, N);
    k_hist<<<edgeBlocks, TB>>>(ei, E);
    k_scan1<<<scanBlocks, TB>>>(N);
    k_scan2<<<1, 512>>>(scanBlocks);
    k_scan3<<<nodeBlocks, TB>>>(N, E);
    k_scatter<<<edgeBlocks, TB>>>(ei, attr, E);

    k_conv<9><<<nodeBlocks, TB>>>(We1, be1, Wo1, bo1, Wx2, bx2, 0, N);
    k_conv<9><<<nodeBlocks, TB>>>(We2, be2, Wo2, bo2, Wx3, bx3, 1, N);
    k_conv<4><<<nodeBlocks, TB>>>(We3, be3, Wo3, bo3, nullptr, nullptr, 0, N);

    k_head<<<(T + TB - 1) / TB, TB>>>(W1, b1, W2, b2, (float*)d_out, T);
}

// round 11
// speedup vs baseline: 1.5254x; 1.1122x over previous
#include <cuda_runtime.h>
#include <cuda_fp16.h>
#include <math.h>

#define NN 1500000
#define EE 12000000
#define HSTRIDE 16  // halves per node record: 9 used + pad -> 32B aligned
#define CH 4096     // staged 8B edge records per chunk (32KB smem)

// ---- device scratch (no allocation allowed) ----
__device__ __half  g_hxA[(size_t)NN * HSTRIDE];  // 48 MB
__device__ __half  g_hxB[(size_t)NN * HSTRIDE];  // 48 MB
__device__ float   g_out4[(size_t)NN * 4];       // 24 MB
__device__ int     g_rowptr[NN + 1];
__device__ int     g_cursor[NN];
__device__ int     g_bsums[1024];
__device__ uint2   g_perm[(size_t)EE];           // 96 MB {src, half2(ax,ay)} by dst

// Pack 9 floats -> fp16 record (uint4 + uint) and store.
__device__ __forceinline__ void store_h9(__half* basePtr, size_t i, const float* h) {
    __half2 p0 = __floats2half2_rn(h[0], h[1]);
    __half2 p1 = __floats2half2_rn(h[2], h[3]);
    __half2 p2 = __floats2half2_rn(h[4], h[5]);
    __half2 p3 = __floats2half2_rn(h[6], h[7]);
    __half2 p4 = __floats2half2_rn(h[8], 0.f);
    uint4 q;
    q.x = *(unsigned int*)&p0;
    q.y = *(unsigned int*)&p1;
    q.z = *(unsigned int*)&p2;
    q.w = *(unsigned int*)&p3;
    unsigned int* rec = (unsigned int*)(basePtr + i * HSTRIDE);
    *(uint4*)rec = q;
    rec[4] = *(unsigned int*)&p4;
}

// Gather 9 fp16 node features -> floats. 2 loads, one 32B sector.
__device__ __forceinline__ void load_h9(const __half* basePtr, size_t i, float* f) {
    const unsigned int* rec = (const unsigned int*)(basePtr + i * HSTRIDE);
    uint4 q = __ldg((const uint4*)rec);
    unsigned int q4 = __ldg(rec + 4);
    float2 a = __half22float2(*(const __half2*)&q.x);
    float2 b = __half22float2(*(const __half2*)&q.y);
    float2 c = __half22float2(*(const __half2*)&q.z);
    float2 d = __half22float2(*(const __half2*)&q.w);
    float2 e = __half22float2(*(const __half2*)&q4);
    f[0] = a.x; f[1] = a.y; f[2] = b.x; f[3] = b.y;
    f[4] = c.x; f[5] = c.y; f[6] = d.x; f[7] = d.y; f[8] = e.x;
}

// ---------------------------------------------------------------------------
__global__ void k_init(const float* __restrict__ x,
                       const float* __restrict__ Wx1,
                       const float* __restrict__ bx1, int n) {
    int i = blockIdx.x * blockDim.x + threadIdx.x;
    if (i >= n) return;
    float xv = x[i];
    float h[9];
#pragma unroll
    for (int j = 0; j < 9; j++) h[j] = fmaf(Wx1[j], xv, bx1[j]);
    store_h9(g_hxA, (size_t)i, h);
    g_cursor[i] = 0;
}

// ---------------------------------------------------------------------------
__global__ void k_hist(const int* __restrict__ ei, int E) {
    int t = blockIdx.x * blockDim.x + threadIdx.x;
    int e0 = t * 4;
    if (e0 >= E) return;
    int4 d4 = *(const int4*)(ei + E + e0);
    atomicAdd(&g_cursor[d4.x], 1);
    atomicAdd(&g_cursor[d4.y], 1);
    atomicAdd(&g_cursor[d4.z], 1);
    atomicAdd(&g_cursor[d4.w], 1);
}

// ---------------------------------------------------------------------------
__global__ void k_scan1(int n) {   // 4096 elems / block
    __shared__ int s[256];
    int tid = threadIdx.x;
    int base = blockIdx.x * 4096 + tid * 16;
    int v[16];
    int sum = 0;
#pragma unroll
    for (int j = 0; j < 16; j++) {
        int idx = base + j;
        v[j] = (idx < n) ? g_cursor[idx] : 0;
        sum += v[j];
    }
    s[tid] = sum;
    __syncthreads();
    for (int off = 1; off < 256; off <<= 1) {
        int t = (tid >= off) ? s[tid - off] : 0;
        __syncthreads();
        s[tid] += t;
        __syncthreads();
    }
    int excl = s[tid] - sum;
    if (tid == 255) g_bsums[blockIdx.x] = s[255];
    int run = excl;
#pragma unroll
    for (int j = 0; j < 16; j++) {
        int idx = base + j;
        if (idx < n) g_rowptr[idx] = run;
        run += v[j];
    }
}

__global__ void k_scan2(int nb) {
    __shared__ int s[512];
    int tid = threadIdx.x;
    int val = (tid < nb) ? g_bsums[tid] : 0;
    s[tid] = val;
    __syncthreads();
    for (int off = 1; off < 512; off <<= 1) {
        int t = (tid >= off) ? s[tid - off] : 0;
        __syncthreads();
        s[tid] += t;
        __syncthreads();
    }
    if (tid < nb) g_bsums[tid] = s[tid] - val;
}

__global__ void k_scan3(int n, int E) {
    int i = blockIdx.x * blockDim.x + threadIdx.x;
    if (i >= n) return;
    int r = g_rowptr[i] + g_bsums[i >> 12];
    g_rowptr[i] = r;
    g_cursor[i] = r;
    if (i == 0) g_rowptr[n] = E;
}

// ---------------------------------------------------------------------------
// Permute edges into dst-sorted order; ONE 8B store per edge.
// ---------------------------------------------------------------------------
__global__ void k_scatter(const int* __restrict__ ei,
                          const float* __restrict__ attr, int E) {
    int t = blockIdx.x * blockDim.x + threadIdx.x;
    int e0 = t * 4;
    if (e0 >= E) return;
    int4 s4 = *(const int4*)(ei + e0);
    int4 d4 = *(const int4*)(ei + E + e0);
    float4 a0 = *(const float4*)(attr + (size_t)e0 * 2);
    float4 a1 = *(const float4*)(attr + (size_t)e0 * 2 + 4);
    int src[4] = {s4.x, s4.y, s4.z, s4.w};
    int dst[4] = {d4.x, d4.y, d4.z, d4.w};
    __half2 at[4] = {__floats2half2_rn(a0.x, a0.y), __floats2half2_rn(a0.z, a0.w),
                     __floats2half2_rn(a1.x, a1.y), __floats2half2_rn(a1.z, a1.w)};
#pragma unroll
    for (int k = 0; k < 4; k++) {
        int pos = atomicAdd(&g_cursor[dst[k]], 1);
        uint2 rec;
        rec.x = (unsigned int)src[k];
        rec.y = *(unsigned int*)&at[k];
        g_perm[pos] = rec;
    }
}

// ---------------------------------------------------------------------------
// Fused conv; SMEM-staged 8B edge records, 4-edge unroll, fp16 gathers.
// ---------------------------------------------------------------------------
template <int OUT>
__global__ void k_conv(const float* __restrict__ We, const float* __restrict__ be,
                       const float* __restrict__ Wo, const float* __restrict__ bo,
                       const float* __restrict__ Wxn, const float* __restrict__ bxn,
                       int srcbuf, int n) {
    __shared__ uint2 sbuf[CH];
    __shared__ float sWe[18], sbe[9], sWo[OUT * 9], sbo[OUT], sWx[81], sbx[9];
    for (int j = threadIdx.x; j < 18; j += blockDim.x) sWe[j] = We[j];
    for (int j = threadIdx.x; j < 9;  j += blockDim.x) sbe[j] = be[j];
    for (int j = threadIdx.x; j < OUT * 9; j += blockDim.x) sWo[j] = Wo[j];
    for (int j = threadIdx.x; j < OUT; j += blockDim.x) sbo[j] = bo[j];
    if (OUT == 9) {
        for (int j = threadIdx.x; j < 81; j += blockDim.x) sWx[j] = Wxn[j];
        for (int j = threadIdx.x; j < 9;  j += blockDim.x) sbx[j] = bxn[j];
    }

    int b0 = blockIdx.x * blockDim.x;
    int i  = b0 + threadIdx.x;
    int beg = 0, end = 0;
    if (i < n) { beg = __ldg(&g_rowptr[i]); end = __ldg(&g_rowptr[i + 1]); }
    int lastNode = min(b0 + (int)blockDim.x, n);
    int beg_blk = __ldg(&g_rowptr[b0]);
    int end_blk = __ldg(&g_rowptr[lastNode]);

    const __half* __restrict__ hin = srcbuf ? g_hxB : g_hxA;
    float acc[9] = {0, 0, 0, 0, 0, 0, 0, 0, 0};

    for (int c0 = beg_blk; c0 < end_blk; c0 += CH) {
        int cnt = min(CH, end_blk - c0);
        __syncthreads();
        // coalesced stage: uint2 per lane (8B x 32 lanes = 2 full lines/warp);
        // no wide-cast -- g_perm[c0] is only guaranteed 8B-aligned.
        for (int j = threadIdx.x; j < cnt; j += blockDim.x)
            sbuf[j] = __ldcs(&g_perm[c0 + j]);
        __syncthreads();

        int lo = max(beg, c0) - c0;
        int hi = min(end, c0 + cnt) - c0;
        int e = lo;
        for (; e + 4 <= hi; e += 4) {
            uint2 r[4];
            float F[4][9];
#pragma unroll
            for (int k = 0; k < 4; k++) r[k] = sbuf[e + k];
#pragma unroll
            for (int k = 0; k < 4; k++) load_h9(hin, (size_t)r[k].x, F[k]);
#pragma unroll
            for (int k = 0; k < 4; k++) {
                float2 a = __half22float2(*(const __half2*)&r[k].y);
                float ew;
#pragma unroll
                for (int j = 0; j < 9; j++) {
                    ew = fmaf(sWe[2 * j], a.x, fmaf(sWe[2 * j + 1], a.y, sbe[j]));
                    acc[j] = fmaf(F[k][j], ew, acc[j]);
                }
            }
        }
        for (; e < hi; e++) {
            uint2 r0 = sbuf[e];
            float A[9];
            load_h9(hin, (size_t)r0.x, A);
            float2 a = __half22float2(*(const __half2*)&r0.y);
#pragma unroll
            for (int j = 0; j < 9; j++) {
                float ew = fmaf(sWe[2 * j], a.x, fmaf(sWe[2 * j + 1], a.y, sbe[j]));
                acc[j] = fmaf(A[j], ew, acc[j]);
            }
        }
    }

    if (i >= n) return;

    if (OUT == 9) {
        float r[9];
#pragma unroll
        for (int o = 0; o < 9; o++) {
            float s = sbo[o];
#pragma unroll
            for (int j = 0; j < 9; j++) s = fmaf(sWo[o * 9 + j], acc[j], s);
            r[o] = fmaxf(s, 0.f);
        }
        float h[9];
#pragma unroll
        for (int o = 0; o < 9; o++) {
            float s = sbx[o];
#pragma unroll
            for (int j = 0; j < 9; j++) s = fmaf(sWx[o * 9 + j], r[j], s);
            h[o] = s;
        }
        __half* hout = srcbuf ? g_hxA : g_hxB;   // ping-pong
        store_h9(hout, (size_t)i, h);
    } else {
        float r[4];
#pragma unroll
        for (int o = 0; o < 4; o++) {
            float s = sbo[o];
#pragma unroll
            for (int j = 0; j < 9; j++) s = fmaf(sWo[o * 9 + j], acc[j], s);
            r[o] = fmaxf(s, 0.f);
        }
        *(float4*)(g_out4 + (size_t)i * 4) = make_float4(r[0], r[1], r[2], r[3]);
    }
}

// ---------------------------------------------------------------------------
__global__ void k_head(const float* __restrict__ W1, const float* __restrict__ b1,
                       const float* __restrict__ W2, const float* __restrict__ b2,
                       float* __restrict__ out, int T) {
    __shared__ float sW1[192], sb1[8], sW2[32], sb2[4];
    for (int j = threadIdx.x; j < 192; j += blockDim.x) sW1[j] = W1[j];
    for (int j = threadIdx.x; j < 8;   j += blockDim.x) sb1[j] = b1[j];
    for (int j = threadIdx.x; j < 32;  j += blockDim.x) sW2[j] = W2[j];
    for (int j = threadIdx.x; j < 4;   j += blockDim.x) sb2[j] = b2[j];
    __syncthreads();

    int t = blockIdx.x * blockDim.x + threadIdx.x;
    if (t >= T) return;

    float v[24];
    const float4* vp = (const float4*)(g_out4 + (size_t)t * 24);
#pragma unroll
    for (int k = 0; k < 6; k++) {
        float4 q = vp[k];
        v[k * 4 + 0] = q.x; v[k * 4 + 1] = q.y;
        v[k * 4 + 2] = q.z; v[k * 4 + 3] = q.w;
    }
    float y1[8];
#pragma unroll
    for (int o = 0; o < 8; o++) {
        float s = sb1[o];
#pragma unroll
        for (int j = 0; j < 24; j++) s = fmaf(sW1[o * 24 + j], v[j], s);
        y1[o] = fmaxf(s, 0.f);
    }
    float y2[4];
#pragma unroll
    for (int o = 0; o < 4; o++) {
        float s = sb2[o];
#pragma unroll
        for (int j = 0; j < 8; j++) s = fmaf(sW2[o * 8 + j], y1[j], s);
        y2[o] = s;
    }
    float mx = fmaxf(fmaxf(y2[0], y2[1]), fmaxf(y2[2], y2[3]));
    float se = expf(y2[0] - mx) + expf(y2[1] - mx) + expf(y2[2] - mx) + expf(y2[3] - mx);
    float lse = mx + logf(se);
    *(float4*)(out + (size_t)t * 4) =
        make_float4(y2[0] - lse, y2[1] - lse, y2[2] - lse, y2[3] - lse);
}

// ---------------------------------------------------------------------------
extern "C" void kernel_launch(void* const* d_in, const int* in_sizes, int n_in,
                              void* d_out, int out_size) {
    const float* x    = (const float*)d_in[0];
    const int*   ei   = (const int*)  d_in[1];
    const float* attr = (const float*)d_in[2];
    const float* Wx1  = (const float*)d_in[3];
    const float* bx1  = (const float*)d_in[4];
    const float* We1  = (const float*)d_in[5];
    const float* be1  = (const float*)d_in[6];
    const float* Wo1  = (const float*)d_in[7];
    const float* bo1  = (const float*)d_in[8];
    const float* Wx2  = (const float*)d_in[9];
    const float* bx2  = (const float*)d_in[10];
    const float* We2  = (const float*)d_in[11];
    const float* be2  = (const float*)d_in[12];
    const float* Wo2  = (const float*)d_in[13];
    const float* bo2  = (const float*)d_in[14];
    const float* Wx3  = (const float*)d_in[15];
    const float* bx3  = (const float*)d_in[16];
    const float* We3  = (const float*)d_in[17];
    const float* be3  = (const float*)d_in[18];
    const float* Wo3  = (const float*)d_in[19];
    const float* bo3  = (const float*)d_in[20];
    const float* W1   = (const float*)d_in[21];
    const float* b1   = (const float*)d_in[22];
    const float* W2   = (const float*)d_in[23];
    const float* b2   = (const float*)d_in[24];

    const int N = in_sizes[0];       // 1,500,000
    const int E = in_sizes[2] / 2;   // 12,000,000
    const int T = N / 6;

    const int TB = 256;
    int nodeBlocks = (N + TB - 1) / TB;
    int edgeBlocks = (E / 4 + TB - 1) / TB;
    int scanBlocks = (N + 4095) / 4096;

    k_init<<<nodeBlocks, TB>>>(x, Wx1, bx1, N);
    k_hist<<<edgeBlocks, TB>>>(ei, E);
    k_scan1<<<scanBlocks, TB>>>(N);
    k_scan2<<<1, 512>>>(scanBlocks);
    k_scan3<<<nodeBlocks, TB>>>(N, E);
    k_scatter<<<edgeBlocks, TB>>>(ei, attr, E);

    k_conv<9><<<nodeBlocks, TB>>>(We1, be1, Wo1, bo1, Wx2, bx2, 0, N);
    k_conv<9><<<nodeBlocks, TB>>>(We2, be2, Wo2, bo2, Wx3, bx3, 1, N);
    k_conv<4><<<nodeBlocks, TB>>>(We3, be3, Wo3, bo3, nullptr, nullptr, 0, N);

    k_head<<<(T + TB - 1) / TB, TB>>>(W1, b1, W2, b2, (float*)d_out, T);
}

// round 16
// speedup vs baseline: 1.7190x; 1.1269x over previous
#include <cuda_runtime.h>
#include <cuda_fp16.h>
#include <cuda_fp8.h>
#include <math.h>

#define NN 1500000
#define EE 12000000
#define CH 4096     // staged 8B edge records per chunk (32KB smem)

// ---- device scratch (no allocation allowed) ----
__device__ uint4   g_hxA[NN];          // 24 MB : 9 x e4m3 node feats, padded 16B
__device__ uint4   g_hxB[NN];          // 24 MB
__device__ float   g_out4[(size_t)NN * 4];   // 24 MB
__device__ int     g_rowptr[NN + 1];
__device__ int     g_cursor[NN];
__device__ int     g_bsums[1024];
__device__ uint2   g_perm[(size_t)EE]; // 96 MB {src, half2(ax,ay)} by dst

// Pack 9 floats -> fp8 e4m3 record (16B) and store with ONE STG.128.
__device__ __forceinline__ void store_f8(uint4* base, size_t i, const float* h) {
    unsigned int p01 = __nv_cvt_float2_to_fp8x2(make_float2(h[0], h[1]), __NV_SATFINITE, __NV_E4M3);
    unsigned int p23 = __nv_cvt_float2_to_fp8x2(make_float2(h[2], h[3]), __NV_SATFINITE, __NV_E4M3);
    unsigned int p45 = __nv_cvt_float2_to_fp8x2(make_float2(h[4], h[5]), __NV_SATFINITE, __NV_E4M3);
    unsigned int p67 = __nv_cvt_float2_to_fp8x2(make_float2(h[6], h[7]), __NV_SATFINITE, __NV_E4M3);
    unsigned int p8  = __nv_cvt_float_to_fp8(h[8], __NV_SATFINITE, __NV_E4M3);
    uint4 q;
    q.x = (p01 & 0xFFFFu) | (p23 << 16);
    q.y = (p45 & 0xFFFFu) | (p67 << 16);
    q.z = p8 & 0xFFu;
    q.w = 0u;
    base[i] = q;
}

// Gather 9 fp8 node features -> floats. ONE LDG.128.
__device__ __forceinline__ void load_f8(const uint4* base, size_t i, float* f) {
    uint4 q = __ldg(base + i);
    __half2_raw r01 = __nv_cvt_fp8x2_to_halfraw2((__nv_fp8x2_storage_t)(q.x & 0xFFFFu), __NV_E4M3);
    __half2_raw r23 = __nv_cvt_fp8x2_to_halfraw2((__nv_fp8x2_storage_t)(q.x >> 16), __NV_E4M3);
    __half2_raw r45 = __nv_cvt_fp8x2_to_halfraw2((__nv_fp8x2_storage_t)(q.y & 0xFFFFu), __NV_E4M3);
    __half2_raw r67 = __nv_cvt_fp8x2_to_halfraw2((__nv_fp8x2_storage_t)(q.y >> 16), __NV_E4M3);
    __half_raw  r8  = __nv_cvt_fp8_to_halfraw((__nv_fp8_storage_t)(q.z & 0xFFu), __NV_E4M3);
    float2 a = __half22float2(*(__half2*)&r01);
    float2 b = __half22float2(*(__half2*)&r23);
    float2 c = __half22float2(*(__half2*)&r45);
    float2 d = __half22float2(*(__half2*)&r67);
    f[0] = a.x; f[1] = a.y; f[2] = b.x; f[3] = b.y;
    f[4] = c.x; f[5] = c.y; f[6] = d.x; f[7] = d.y;
    f[8] = __half2float(*(__half*)&r8);
}

// ---------------------------------------------------------------------------
__global__ void k_init(const float* __restrict__ x,
                       const float* __restrict__ Wx1,
                       const float* __restrict__ bx1, int n) {
    int i = blockIdx.x * blockDim.x + threadIdx.x;
    if (i >= n) return;
    float xv = x[i];
    float h[9];
#pragma unroll
    for (int j = 0; j < 9; j++) h[j] = fmaf(Wx1[j], xv, bx1[j]);
    store_f8(g_hxA, (size_t)i, h);
    g_cursor[i] = 0;
}

// ---------------------------------------------------------------------------
__global__ void k_hist(const int* __restrict__ ei, int E) {
    int t = blockIdx.x * blockDim.x + threadIdx.x;
    int e0 = t * 4;
    if (e0 >= E) return;
    int4 d4 = *(const int4*)(ei + E + e0);
    atomicAdd(&g_cursor[d4.x], 1);
    atomicAdd(&g_cursor[d4.y], 1);
    atomicAdd(&g_cursor[d4.z], 1);
    atomicAdd(&g_cursor[d4.w], 1);
}

// ---------------------------------------------------------------------------
__global__ void k_scan1(int n) {   // 4096 elems / block
    __shared__ int s[256];
    int tid = threadIdx.x;
    int base = blockIdx.x * 4096 + tid * 16;
    int v[16];
    int sum = 0;
#pragma unroll
    for (int j = 0; j < 16; j++) {
        int idx = base + j;
        v[j] = (idx < n) ? g_cursor[idx] : 0;
        sum += v[j];
    }
    s[tid] = sum;
    __syncthreads();
    for (int off = 1; off < 256; off <<= 1) {
        int t = (tid >= off) ? s[tid - off] : 0;
        __syncthreads();
        s[tid] += t;
        __syncthreads();
    }
    int excl = s[tid] - sum;
    if (tid == 255) g_bsums[blockIdx.x] = s[255];
    int run = excl;
#pragma unroll
    for (int j = 0; j < 16; j++) {
        int idx = base + j;
        if (idx < n) g_rowptr[idx] = run;
        run += v[j];
    }
}

__global__ void k_scan2(int nb) {
    __shared__ int s[512];
    int tid = threadIdx.x;
    int val = (tid < nb) ? g_bsums[tid] : 0;
    s[tid] = val;
    __syncthreads();
    for (int off = 1; off < 512; off <<= 1) {
        int t = (tid >= off) ? s[tid - off] : 0;
        __syncthreads();
        s[tid] += t;
        __syncthreads();
    }
    if (tid < nb) g_bsums[tid] = s[tid] - val;
}

__global__ void k_scan3(int n, int E) {
    int i = blockIdx.x * blockDim.x + threadIdx.x;
    if (i >= n) return;
    int r = g_rowptr[i] + g_bsums[i >> 12];
    g_rowptr[i] = r;
    g_cursor[i] = r;
    if (i == 0) g_rowptr[n] = E;
}

// ---------------------------------------------------------------------------
// Permute edges into dst-sorted order; ONE 8B store per edge.
// ---------------------------------------------------------------------------
__global__ void k_scatter(const int* __restrict__ ei,
                          const float* __restrict__ attr, int E) {
    int t = blockIdx.x * blockDim.x + threadIdx.x;
    int e0 = t * 4;
    if (e0 >= E) return;
    int4 s4 = *(const int4*)(ei + e0);
    int4 d4 = *(const int4*)(ei + E + e0);
    float4 a0 = *(const float4*)(attr + (size_t)e0 * 2);
    float4 a1 = *(const float4*)(attr + (size_t)e0 * 2 + 4);
    int src[4] = {s4.x, s4.y, s4.z, s4.w};
    int dst[4] = {d4.x, d4.y, d4.z, d4.w};
    __half2 at[4] = {__floats2half2_rn(a0.x, a0.y), __floats2half2_rn(a0.z, a0.w),
                     __floats2half2_rn(a1.x, a1.y), __floats2half2_rn(a1.z, a1.w)};
#pragma unroll
    for (int k = 0; k < 4; k++) {
        int pos = atomicAdd(&g_cursor[dst[k]], 1);
        uint2 rec;
        rec.x = (unsigned int)src[k];
        rec.y = *(unsigned int*)&at[k];
        g_perm[pos] = rec;
    }
}

// ---------------------------------------------------------------------------
// Fused conv; SMEM-staged 8B edge records, 4-edge unroll, fp8 gathers (1 wf).
// ---------------------------------------------------------------------------
template <int OUT>
__global__ void k_conv(const float* __restrict__ We, const float* __restrict__ be,
                       const float* __restrict__ Wo, const float* __restrict__ bo,
                       const float* __restrict__ Wxn, const float* __restrict__ bxn,
                       int srcbuf, int n) {
    __shared__ uint2 sbuf[CH];
    __shared__ float sWe[18], sbe[9], sWo[OUT * 9], sbo[OUT], sWx[81], sbx[9];
    for (int j = threadIdx.x; j < 18; j += blockDim.x) sWe[j] = We[j];
    for (int j = threadIdx.x; j < 9;  j += blockDim.x) sbe[j] = be[j];
    for (int j = threadIdx.x; j < OUT * 9; j += blockDim.x) sWo[j] = Wo[j];
    for (int j = threadIdx.x; j < OUT; j += blockDim.x) sbo[j] = bo[j];
    if (OUT == 9) {
        for (int j = threadIdx.x; j < 81; j += blockDim.x) sWx[j] = Wxn[j];
        for (int j = threadIdx.x; j < 9;  j += blockDim.x) sbx[j] = bxn[j];
    }

    int b0 = blockIdx.x * blockDim.x;
    int i  = b0 + threadIdx.x;
    int beg = 0, end = 0;
    if (i < n) { beg = __ldg(&g_rowptr[i]); end = __ldg(&g_rowptr[i + 1]); }
    int lastNode = min(b0 + (int)blockDim.x, n);
    int beg_blk = __ldg(&g_rowptr[b0]);
    int end_blk = __ldg(&g_rowptr[lastNode]);

    const uint4* __restrict__ hin = srcbuf ? g_hxB : g_hxA;
    float acc[9] = {0, 0, 0, 0, 0, 0, 0, 0, 0};

    for (int c0 = beg_blk; c0 < end_blk; c0 += CH) {
        int cnt = min(CH, end_blk - c0);
        __syncthreads();
        // coalesced stage: uint2 per lane; g_perm[c0] is only 8B-aligned.
        for (int j = threadIdx.x; j < cnt; j += blockDim.x)
            sbuf[j] = __ldcs(&g_perm[c0 + j]);
        __syncthreads();

        int lo = max(beg, c0) - c0;
        int hi = min(end, c0 + cnt) - c0;
        int e = lo;
        for (; e + 4 <= hi; e += 4) {
            uint2 r[4];
            float F[4][9];
#pragma unroll
            for (int k = 0; k < 4; k++) r[k] = sbuf[e + k];
#pragma unroll
            for (int k = 0; k < 4; k++) load_f8(hin, (size_t)r[k].x, F[k]);
#pragma unroll
            for (int k = 0; k < 4; k++) {
                float2 a = __half22float2(*(const __half2*)&r[k].y);
                float ew;
#pragma unroll
                for (int j = 0; j < 9; j++) {
                    ew = fmaf(sWe[2 * j], a.x, fmaf(sWe[2 * j + 1], a.y, sbe[j]));
                    acc[j] = fmaf(F[k][j], ew, acc[j]);
                }
            }
        }
        for (; e < hi; e++) {
            uint2 r0 = sbuf[e];
            float A[9];
            load_f8(hin, (size_t)r0.x, A);
            float2 a = __half22float2(*(const __half2*)&r0.y);
#pragma unroll
            for (int j = 0; j < 9; j++) {
                float ew = fmaf(sWe[2 * j], a.x, fmaf(sWe[2 * j + 1], a.y, sbe[j]));
                acc[j] = fmaf(A[j], ew, acc[j]);
            }
        }
    }

    if (i >= n) return;

    if (OUT == 9) {
        float r[9];
#pragma unroll
        for (int o = 0; o < 9; o++) {
            float s = sbo[o];
#pragma unroll
            for (int j = 0; j < 9; j++) s = fmaf(sWo[o * 9 + j], acc[j], s);
            r[o] = fmaxf(s, 0.f);
        }
        float h[9];
#pragma unroll
        for (int o = 0; o < 9; o++) {
            float s = sbx[o];
#pragma unroll
            for (int j = 0; j < 9; j++) s = fmaf(sWx[o * 9 + j], r[j], s);
            h[o] = s;
        }
        uint4* hout = srcbuf ? g_hxA : g_hxB;   // ping-pong
        store_f8(hout, (size_t)i, h);
    } else {
        float r[4];
#pragma unroll
        for (int o = 0; o < 4; o++) {
            float s = sbo[o];
#pragma unroll
            for (int j = 0; j < 9; j++) s = fmaf(sWo[o * 9 + j], acc[j], s);
            r[o] = fmaxf(s, 0.f);
        }
        *(float4*)(g_out4 + (size_t)i * 4) = make_float4(r[0], r[1], r[2], r[3]);
    }
}

// ---------------------------------------------------------------------------
__global__ void k_head(const float* __restrict__ W1, const float* __restrict__ b1,
                       const float* __restrict__ W2, const float* __restrict__ b2,
                       float* __restrict__ out, int T) {
    __shared__ float sW1[192], sb1[8], sW2[32], sb2[4];
    for (int j = threadIdx.x; j < 192; j += blockDim.x) sW1[j] = W1[j];
    for (int j = threadIdx.x; j < 8;   j += blockDim.x) sb1[j] = b1[j];
    for (int j = threadIdx.x; j < 32;  j += blockDim.x) sW2[j] = W2[j];
    for (int j = threadIdx.x; j < 4;   j += blockDim.x) sb2[j] = b2[j];
    __syncthreads();

    int t = blockIdx.x * blockDim.x + threadIdx.x;
    if (t >= T) return;

    float v[24];
    const float4* vp = (const float4*)(g_out4 + (size_t)t * 24);
#pragma unroll
    for (int k = 0; k < 6; k++) {
        float4 q = vp[k];
        v[k * 4 + 0] = q.x; v[k * 4 + 1] = q.y;
        v[k * 4 + 2] = q.z; v[k * 4 + 3] = q.w;
    }
    float y1[8];
#pragma unroll
    for (int o = 0; o < 8; o++) {
        float s = sb1[o];
#pragma unroll
        for (int j = 0; j < 24; j++) s = fmaf(sW1[o * 24 + j], v[j], s);
        y1[o] = fmaxf(s, 0.f);
    }
    float y2[4];
#pragma unroll
    for (int o = 0; o < 4; o++) {
        float s = sb2[o];
#pragma unroll
        for (int j = 0; j < 8; j++) s = fmaf(sW2[o * 8 + j], y1[j], s);
        y2[o] = s;
    }
    float mx = fmaxf(fmaxf(y2[0], y2[1]), fmaxf(y2[2], y2[3]));
    float se = expf(y2[0] - mx) + expf(y2[1] - mx) + expf(y2[2] - mx) + expf(y2[3] - mx);
    float lse = mx + logf(se);
    *(float4*)(out + (size_t)t * 4) =
        make_float4(y2[0] - lse, y2[1] - lse, y2[2] - lse, y2[3] - lse);
}

// ---------------------------------------------------------------------------
extern "C" void kernel_launch(void* const* d_in, const int* in_sizes, int n_in,
                              void* d_out, int out_size) {
    const float* x    = (const float*)d_in[0];
    const int*   ei   = (const int*)  d_in[1];
    const float* attr = (const float*)d_in[2];
    const float* Wx1  = (const float*)d_in[3];
    const float* bx1  = (const float*)d_in[4];
    const float* We1  = (const float*)d_in[5];
    const float* be1  = (const float*)d_in[6];
    const float* Wo1  = (const float*)d_in[7];
    const float* bo1  = (const float*)d_in[8];
    const float* Wx2  = (const float*)d_in[9];
    const float* bx2  = (const float*)d_in[10];
    const float* We2  = (const float*)d_in[11];
    const float* be2  = (const float*)d_in[12];
    const float* Wo2  = (const float*)d_in[13];
    const float* bo2  = (const float*)d_in[14];
    const float* Wx3  = (const float*)d_in[15];
    const float* bx3  = (const float*)d_in[16];
    const float* We3  = (const float*)d_in[17];
    const float* be3  = (const float*)d_in[18];
    const float* Wo3  = (const float*)d_in[19];
    const float* bo3  = (const float*)d_in[20];
    const float* W1   = (const float*)d_in[21];
    const float* b1   = (const float*)d_in[22];
    const float* W2   = (const float*)d_in[23];
    const float* b2   = (const float*)d_in[24];

    const int N = in_sizes[0];       // 1,500,000
    const int E = in_sizes[2] / 2;   // 12,000,000
    const int T = N / 6;

    const int TB = 256;
    int nodeBlocks = (N + TB - 1) / TB;
    int edgeBlocks = (E / 4 + TB - 1) / TB;
    int scanBlocks = (N + 4095) / 4096;

    k_init<<<nodeBlocks, TB>>>(x, Wx1, bx1, N);
    k_hist<<<edgeBlocks, TB>>>(ei, E);
    k_scan1<<<scanBlocks, TB>>>(N);
    k_scan2<<<1, 512>>>(scanBlocks);
    k_scan3<<<nodeBlocks, TB>>>(N, E);
    k_scatter<<<edgeBlocks, TB>>>(ei, attr, E);

    k_conv<9><<<nodeBlocks, TB>>>(We1, be1, Wo1, bo1, Wx2, bx2, 0, N);
    k_conv<9><<<nodeBlocks, TB>>>(We2, be2, Wo2, bo2, Wx3, bx3, 1, N);
    k_conv<4><<<nodeBlocks, TB>>>(We3, be3, Wo3, bo3, nullptr, nullptr, 0, N);

    k_head<<<(T + TB - 1) / TB, TB>>>(W1, b1, W2, b2, (float*)d_out, T);
}